// round 16
// baseline (speedup 1.0000x reference)
#include <cuda_runtime.h>
#include <cstdint>

// SparseEdgeDrop (layouts confirmed):
//   in:  edge_index int32 [2E], edge_values f32 [E], mask int32 0/1 [E]
//   out: [ (float)edge_index (2E) | mask ? val * 1/(0.8+1e-5) : 0 (E) ]
// ~896 MB touch-once streaming, HBM-bound.
//
// Policy A/B results: stores __stcs(84.7%) > default(82.7-84.0%) > __stwt(81.2%);
// reads __ldcs. This round: persistent one-wave grid-stride launch (148*8 CTAs)
// to remove 83 waves of CTA launch/retire churn; two section loops, no
// per-quad branch.

static constexpr float kScale = (float)(1.0 / (1.0 - 0.2 + 1e-5));

static constexpr int kThreads      = 256;
static constexpr int kCtasPerSM    = 8;     // 256 thr * 32 regs * 8 = 64K regs/SM
static constexpr int kNumSMs       = 148;
static constexpr int kGridPersist  = kNumSMs * kCtasPerSM;  // 1184

__global__ void __launch_bounds__(kThreads, kCtasPerSM)
sparse_edge_drop_persist(const int4*   __restrict__ idx4,
                         const float4* __restrict__ vals4,
                         const int4*   __restrict__ mask4,
                         float4*       __restrict__ out4,
                         long long nIdx4,   // 2E/4
                         long long nVal4)   // E/4
{
    const long long tid    = (long long)blockIdx.x * blockDim.x + threadIdx.x;
    const long long stride = (long long)gridDim.x * blockDim.x;

    // Section 1: index convert, one 16B quad per iteration.
    for (long long i = tid; i < nIdx4; i += stride) {
        int4 a = __ldcs(&idx4[i]);
        float4 o;
        o.x = (float)a.x;
        o.y = (float)a.y;
        o.z = (float)a.z;
        o.w = (float)a.w;
        __stcs(&out4[i], o);
    }

    // Section 2: masked scale, one 16B quad per iteration (2 front-batched loads).
    float4* __restrict__ outv = out4 + nIdx4;
    for (long long j = tid; j < nVal4; j += stride) {
        float4 v = __ldcs(&vals4[j]);
        int4   m = __ldcs(&mask4[j]);
        float4 o;
        o.x = m.x ? v.x * kScale : 0.0f;
        o.y = m.y ? v.y * kScale : 0.0f;
        o.z = m.z ? v.z * kScale : 0.0f;
        o.w = m.w ? v.w * kScale : 0.0f;
        __stcs(&outv[j], o);
    }
}

// Val-only fallback (out_size == E layout; not expected, kept for safety).
__global__ void __launch_bounds__(kThreads, kCtasPerSM)
sparse_edge_drop_vals(const float4* __restrict__ vals4,
                      const int4*   __restrict__ mask4,
                      float4*       __restrict__ out4,
                      long long nVal4)
{
    const long long tid    = (long long)blockIdx.x * blockDim.x + threadIdx.x;
    const long long stride = (long long)gridDim.x * blockDim.x;
    for (long long j = tid; j < nVal4; j += stride) {
        float4 v = __ldcs(&vals4[j]);
        int4   m = __ldcs(&mask4[j]);
        float4 o;
        o.x = m.x ? v.x * kScale : 0.0f;
        o.y = m.y ? v.y * kScale : 0.0f;
        o.z = m.z ? v.z * kScale : 0.0f;
        o.w = m.w ? v.w * kScale : 0.0f;
        __stcs(&out4[j], o);
    }
}

extern "C" void kernel_launch(void* const* d_in, const int* in_sizes, int n_in,
                              void* d_out, int out_size)
{
    const int4*   idx4  = (const int4*)d_in[0];
    const float4* vals4 = (const float4*)d_in[1];
    const int4*   mask4 = (const int4*)d_in[2];

    const long long E     = (long long)in_sizes[1];   // 2^25
    const long long nVal4 = E / 4;

    float4* out4 = (float4*)d_out;

    if ((long long)out_size >= 3 * E) {
        const long long nIdx4 = (2 * E) / 4;
        sparse_edge_drop_persist<<<kGridPersist, kThreads>>>(
            idx4, vals4, mask4, out4, nIdx4, nVal4);
    } else {
        sparse_edge_drop_vals<<<kGridPersist, kThreads>>>(
            vals4, mask4, out4, nVal4);
    }
}

// round 17
// speedup vs baseline: 1.0964x; 1.0964x over previous
#include <cuda_runtime.h>
#include <cstdint>

// SparseEdgeDrop (layouts confirmed):
//   in:  edge_index int32 [2E], edge_values f32 [E], mask int32 0/1 [E]
//   out: [ (float)edge_index (2E) | mask ? val * 1/(0.8+1e-5) : 0 (E) ]
// ~896 MB touch-once streaming, HBM-bound.
//
// A/B matrix (kernel us / DRAM%):
//   R12 plain 1q flat        134.5 / 84.0
//   R13 ldcs+stcs 2q flat    133.2 / 84.7   <- best policy
//   R14 stwt                 137.7 / 81.2   (write-through: no L2 coalescing)
//   R15 default-WB 2q        135.1 / 82.7   (lazy dirty drain worse than stcs)
//   R16 persistent stride    139.0 / 81.8   (stride kills page locality)
// Final cell: 1-quad flat shape (16 regs, contiguous per-CTA windows)
// + ldcs/stcs policy.

static constexpr float kScale = (float)(1.0 / (1.0 - 0.2 + 1e-5));

__global__ void __launch_bounds__(256)
sparse_edge_drop_final(const int4*   __restrict__ idx4,
                       const float4* __restrict__ vals4,
                       const int4*   __restrict__ mask4,
                       float4*       __restrict__ out4,
                       long long nIdx4,   // 2E/4
                       long long nVal4)   // E/4
{
    long long i = (long long)blockIdx.x * blockDim.x + threadIdx.x;
    if (i < nIdx4) {
        // Index section: one LDG.128 (evict-first) + one STG.128 (evict-first)
        int4 a = __ldcs(&idx4[i]);
        float4 o;
        o.x = (float)a.x;
        o.y = (float)a.y;
        o.z = (float)a.z;
        o.w = (float)a.w;
        __stcs(&out4[i], o);
    } else {
        long long j = i - nIdx4;
        if (j < nVal4) {
            // Val section: two front-batched LDG.128 + one STG.128
            float4 v = __ldcs(&vals4[j]);
            int4   m = __ldcs(&mask4[j]);
            float4 o;
            o.x = m.x ? v.x * kScale : 0.0f;
            o.y = m.y ? v.y * kScale : 0.0f;
            o.z = m.z ? v.z * kScale : 0.0f;
            o.w = m.w ? v.w * kScale : 0.0f;
            __stcs(&out4[nIdx4 + j], o);
        }
    }
}

// Val-only fallback (out_size == E layout; not expected, kept for safety).
__global__ void __launch_bounds__(256)
sparse_edge_drop_vals(const float4* __restrict__ vals4,
                      const int4*   __restrict__ mask4,
                      float4*       __restrict__ out4,
                      long long nVal4)
{
    long long j = (long long)blockIdx.x * blockDim.x + threadIdx.x;
    if (j >= nVal4) return;
    float4 v = __ldcs(&vals4[j]);
    int4   m = __ldcs(&mask4[j]);
    float4 o;
    o.x = m.x ? v.x * kScale : 0.0f;
    o.y = m.y ? v.y * kScale : 0.0f;
    o.z = m.z ? v.z * kScale : 0.0f;
    o.w = m.w ? v.w * kScale : 0.0f;
    __stcs(&out4[j], o);
}

extern "C" void kernel_launch(void* const* d_in, const int* in_sizes, int n_in,
                              void* d_out, int out_size)
{
    const int4*   idx4  = (const int4*)d_in[0];
    const float4* vals4 = (const float4*)d_in[1];
    const int4*   mask4 = (const int4*)d_in[2];

    const long long E     = (long long)in_sizes[1];   // 2^25
    const long long nVal4 = E / 4;

    float4* out4 = (float4*)d_out;

    if ((long long)out_size >= 3 * E) {
        const long long nIdx4  = (2 * E) / 4;
        const long long total4 = nIdx4 + nVal4;
        const int threads = 256;
        const long long blocks = (total4 + threads - 1) / threads;
        sparse_edge_drop_final<<<(unsigned)blocks, threads>>>(
            idx4, vals4, mask4, out4, nIdx4, nVal4);
    } else {
        const int threads = 256;
        const long long blocks = (nVal4 + threads - 1) / threads;
        sparse_edge_drop_vals<<<(unsigned)blocks, threads>>>(
            vals4, mask4, out4, nVal4);
    }
}